// round 2
// baseline (speedup 1.0000x reference)
#include <cuda_runtime.h>

#define ALPHA 0.2f

// ---------------- persistent scratch (device globals, no allocation) ----------------
__device__ float g_WhH[4 * 4096 * 64];   // per-head Wh
__device__ float g_WhO[4096 * 64];       // out-layer Wh
__device__ float g_xres[4096 * 64];      // x @ lin_w^T + lin_b
__device__ float g_hcat[4096 * 256];     // elu(head outputs), concatenated
__device__ float g_attO[4096 * 64];      // out-layer attention output (elu'd)
__device__ float g_s[5 * 4096];          // per-node source scores (4 heads + out)
__device__ float g_t[5 * 4096];          // per-node target scores

// ---------------- helpers ----------------
__device__ __forceinline__ float elu1(float v) {
    return v > 0.f ? v : (__expf(v) - 1.f);
}

__device__ __forceinline__ float scorep(float sv, float tv, int m) {
    float e = sv + tv;
    e = e > 0.f ? e : ALPHA * e;
    return m > 0 ? __expf(e) : 0.f;
}

// pack a float into both lanes of an f32x2 register
__device__ __forceinline__ unsigned long long pk2(float a) {
    unsigned long long r;
    unsigned int b = __float_as_uint(a);
    asm("mov.b64 %0, {%1, %1};" : "=l"(r) : "r"(b));
    return r;
}

__device__ __forceinline__ void ffma2(unsigned long long& d, unsigned long long a,
                                      unsigned long long b) {
    asm("fma.rn.f32x2 %0, %1, %2, %0;" : "+l"(d) : "l"(a), "l"(b));
}

__device__ __forceinline__ float2 upk(unsigned long long v) {
    unsigned int lo, hi;
    asm("mov.b64 {%0, %1}, %2;" : "=r"(lo), "=r"(hi) : "l"(v));
    return make_float2(__uint_as_float(lo), __uint_as_float(hi));
}

// ---------------- Kernel A: Wh for 4 heads + x_residual ----------------
// x[4096,128] @ { w_heads[h][128,64] (h=0..3), lin_w^T[128,64] }  -> g_WhH, g_xres
__global__ __launch_bounds__(256) void kA(const float* __restrict__ x,
                                          const float* __restrict__ w_heads,
                                          const float* __restrict__ lin_w,
                                          const float* __restrict__ lin_b) {
    __shared__ float xs[32 * 132];
    __shared__ float ws[64 * 68];
    const int tid = threadIdx.x;
    const int i0 = blockIdx.x * 32;

    // load 32 x-rows
#pragma unroll
    for (int u = 0; u < 16; u++) {
        int idx = tid + 256 * u;
        int r = idx >> 7, f = idx & 127;
        xs[r * 132 + f] = x[(i0 + r) * 128 + f];
    }

    const int r = tid >> 3, g = tid & 7;

    for (int cc = 0; cc < 5; cc++) {
        float acc[8];
#pragma unroll
        for (int u = 0; u < 8; u++) acc[u] = 0.f;

        for (int fh = 0; fh < 2; fh++) {
            __syncthreads();
            if (cc < 4) {
#pragma unroll
                for (int u = 0; u < 4; u++) {
                    int f4 = tid + 256 * u;
                    int jj = f4 >> 4, kq = (f4 & 15) * 4;
                    *(float4*)&ws[jj * 68 + kq] =
                        *(const float4*)&w_heads[(cc * 128 + fh * 64 + jj) * 64 + kq];
                }
            } else {
#pragma unroll
                for (int u = 0; u < 16; u++) {
                    int idx = tid + 256 * u;
                    int k = idx >> 6, fo = idx & 63;
                    ws[fo * 68 + k] = lin_w[k * 128 + fh * 64 + fo];
                }
            }
            __syncthreads();
#pragma unroll 8
            for (int fo = 0; fo < 64; fo++) {
                float xv = xs[r * 132 + fh * 64 + fo];
                float4 w0 = *(float4*)&ws[fo * 68 + g * 4];
                float4 w1 = *(float4*)&ws[fo * 68 + 32 + g * 4];
                acc[0] += xv * w0.x; acc[1] += xv * w0.y;
                acc[2] += xv * w0.z; acc[3] += xv * w0.w;
                acc[4] += xv * w1.x; acc[5] += xv * w1.y;
                acc[6] += xv * w1.z; acc[7] += xv * w1.w;
            }
        }

        if (cc < 4) {
            float* dst = g_WhH + ((size_t)(cc * 4096) + i0 + r) * 64;
            *(float4*)(dst + g * 4) = make_float4(acc[0], acc[1], acc[2], acc[3]);
            *(float4*)(dst + 32 + g * 4) = make_float4(acc[4], acc[5], acc[6], acc[7]);
        } else {
            float* dst = g_xres + ((size_t)(i0 + r)) * 64;
            float4 oa = make_float4(acc[0] + lin_b[g * 4 + 0], acc[1] + lin_b[g * 4 + 1],
                                    acc[2] + lin_b[g * 4 + 2], acc[3] + lin_b[g * 4 + 3]);
            float4 ob = make_float4(acc[4] + lin_b[32 + g * 4 + 0], acc[5] + lin_b[32 + g * 4 + 1],
                                    acc[6] + lin_b[32 + g * 4 + 2], acc[7] + lin_b[32 + g * 4 + 3]);
            *(float4*)(dst + g * 4) = oa;
            *(float4*)(dst + 32 + g * 4) = ob;
        }
    }
}

// ---------------- Kernel B: per-head s,t scalars ----------------
__global__ __launch_bounds__(256) void kB(const float* __restrict__ a_heads) {
    const int wid = blockIdx.x * 8 + (threadIdx.x >> 5);
    const int lane = threadIdx.x & 31;
    const int h = wid >> 12, i = wid & 4095;
    const float* wr = g_WhH + ((size_t)h * 4096 + i) * 64;
    float v0 = wr[lane], v1 = wr[32 + lane];
    const float* a = a_heads + h * 128;
    float sp = v0 * a[lane] + v1 * a[32 + lane];
    float tp = v0 * a[64 + lane] + v1 * a[96 + lane];
#pragma unroll
    for (int m = 16; m; m >>= 1) {
        sp += __shfl_xor_sync(0xffffffffu, sp, m);
        tp += __shfl_xor_sync(0xffffffffu, tp, m);
    }
    if (lane == 0) {
        g_s[h * 4096 + i] = sp;
        g_t[h * 4096 + i] = tp;
    }
}

// ---------------- Kernel C: fused masked-softmax attention aggregation ----------------
// mode 0: 4 heads -> g_hcat (elu);  mode 1: out layer -> g_attO (elu)
__global__ __launch_bounds__(256) void kC(const int* __restrict__ adj, int mode) {
    __shared__ float whs[64 * 68];
    __shared__ float Ps[32 * 65];
    __shared__ float den[32];
    const int tid = threadIdx.x;
    const int hb = blockIdx.y;
    const int i0 = blockIdx.x * 32;

    const float *Wh, *sh, *th;
    float* outp;
    int ostride, coloff;
    if (mode == 0) {
        Wh = g_WhH + (size_t)hb * 4096 * 64;
        sh = g_s + hb * 4096;
        th = g_t + hb * 4096;
        outp = g_hcat; ostride = 256; coloff = hb * 64;
    } else {
        Wh = g_WhO;
        sh = g_s + 4 * 4096;
        th = g_t + 4 * 4096;
        outp = g_attO; ostride = 64; coloff = 0;
    }

    const int r1 = tid >> 3, g1 = tid & 7;     // phase-1 mapping: row r1, j-subgroup g1
    const int lane = tid & 31, wq = tid >> 5;  // phase-2 mapping: row lane, k-group wq
    const float sv = sh[i0 + r1];
    float dpart = 0.f;
    unsigned long long acc0 = 0ull, acc1 = 0ull, acc2 = 0ull, acc3 = 0ull;

    const int* arow = adj + (i0 + r1) * 4096 + g1 * 8;
    const float* trow = th + g1 * 8;

    for (int jt = 0; jt < 64; jt++) {
        const int j0 = jt * 64;
        __syncthreads();
        // stage Wh tile [64 x 64]
#pragma unroll
        for (int u = 0; u < 4; u++) {
            int f4 = tid + 256 * u;
            int jj = f4 >> 4, kq = (f4 & 15) * 4;
            *(float4*)&whs[jj * 68 + kq] = *(const float4*)&Wh[(size_t)(j0 + jj) * 64 + kq];
        }
        // phase 1: scores -> P
        int4 a0 = *(const int4*)(arow + j0);
        int4 a1 = *(const int4*)(arow + j0 + 4);
        float4 t0 = *(const float4*)(trow + j0);
        float4 t1 = *(const float4*)(trow + j0 + 4);
        float p0 = scorep(sv, t0.x, a0.x);
        float p1 = scorep(sv, t0.y, a0.y);
        float p2 = scorep(sv, t0.z, a0.z);
        float p3 = scorep(sv, t0.w, a0.w);
        float p4 = scorep(sv, t1.x, a1.x);
        float p5 = scorep(sv, t1.y, a1.y);
        float p6 = scorep(sv, t1.z, a1.z);
        float p7 = scorep(sv, t1.w, a1.w);
        float* Pb = Ps + r1 * 65 + g1 * 8;
        Pb[0] = p0; Pb[1] = p1; Pb[2] = p2; Pb[3] = p3;
        Pb[4] = p4; Pb[5] = p5; Pb[6] = p6; Pb[7] = p7;
        dpart += ((p0 + p1) + (p2 + p3)) + ((p4 + p5) + (p6 + p7));
        __syncthreads();
        // phase 2: numer += P * Wh  (packed f32x2 FMAs)
        const float* Prow = Ps + lane * 65;
#pragma unroll 8
        for (int jj = 0; jj < 64; jj++) {
            unsigned long long pp = pk2(Prow[jj]);
            const float* wr = whs + jj * 68 + wq * 4;
            ulonglong2 wA = *(const ulonglong2*)wr;
            ulonglong2 wB = *(const ulonglong2*)(wr + 32);
            ffma2(acc0, pp, wA.x);
            ffma2(acc1, pp, wA.y);
            ffma2(acc2, pp, wB.x);
            ffma2(acc3, pp, wB.y);
        }
    }

    // reduce denominators over the 8 j-subgroups of each row
    dpart += __shfl_xor_sync(0xffffffffu, dpart, 1);
    dpart += __shfl_xor_sync(0xffffffffu, dpart, 2);
    dpart += __shfl_xor_sync(0xffffffffu, dpart, 4);
    if (g1 == 0) den[r1] = dpart;
    __syncthreads();

    const float dinv = 1.f / den[lane];
    float2 f0 = upk(acc0), f1 = upk(acc1), f2 = upk(acc2), f3 = upk(acc3);
    float* dst = outp + (size_t)(i0 + lane) * ostride + coloff;
    float4 oa = make_float4(elu1(f0.x * dinv), elu1(f0.y * dinv),
                            elu1(f1.x * dinv), elu1(f1.y * dinv));
    float4 ob = make_float4(elu1(f2.x * dinv), elu1(f2.y * dinv),
                            elu1(f3.x * dinv), elu1(f3.y * dinv));
    *(float4*)(dst + wq * 4) = oa;
    *(float4*)(dst + 32 + wq * 4) = ob;
}

// ---------------- Kernel E: out-layer Wh = hcat @ w_out, plus s,t ----------------
__global__ __launch_bounds__(256) void kE(const float* __restrict__ w_out,
                                          const float* __restrict__ a_out) {
    __shared__ float hc[16 * 260];
    __shared__ float ws[64 * 68];
    const int tid = threadIdx.x;
    const int i0 = blockIdx.x * 16;

#pragma unroll
    for (int u = 0; u < 4; u++) {
        int f4 = tid + 256 * u;
        int r = f4 >> 6, cq = (f4 & 63) * 4;
        *(float4*)&hc[r * 260 + cq] = *(const float4*)&g_hcat[(size_t)(i0 + r) * 256 + cq];
    }

    const int r2 = tid >> 4, g2 = tid & 15;
    float acc[4] = {0.f, 0.f, 0.f, 0.f};

    for (int fc = 0; fc < 4; fc++) {
        __syncthreads();
#pragma unroll
        for (int u = 0; u < 4; u++) {
            int f4 = tid + 256 * u;
            int jj = f4 >> 4, kq = (f4 & 15) * 4;
            *(float4*)&ws[jj * 68 + kq] = *(const float4*)&w_out[(fc * 64 + jj) * 64 + kq];
        }
        __syncthreads();
#pragma unroll 8
        for (int fo = 0; fo < 64; fo++) {
            float xv = hc[r2 * 260 + fc * 64 + fo];
            float4 wv = *(float4*)&ws[fo * 68 + g2 * 4];
            acc[0] += xv * wv.x; acc[1] += xv * wv.y;
            acc[2] += xv * wv.z; acc[3] += xv * wv.w;
        }
    }

    float* dst = g_WhO + (size_t)(i0 + r2) * 64 + g2 * 4;
    *(float4*)dst = make_float4(acc[0], acc[1], acc[2], acc[3]);
    __syncthreads();

    if (tid < 16) {
        const float* wr = g_WhO + (size_t)(i0 + tid) * 64;
        float sAcc = 0.f, tAcc = 0.f;
        for (int k = 0; k < 64; k++) {
            float v = wr[k];
            sAcc += v * a_out[k];
            tAcc += v * a_out[64 + k];
        }
        g_s[4 * 4096 + i0 + tid] = sAcc;
        g_t[4 * 4096 + i0 + tid] = tAcc;
    }
}

// ---------------- Kernel G: final linear + elu -> d_out ----------------
__global__ __launch_bounds__(256) void kG(const float* __restrict__ outlin_w,
                                          const float* __restrict__ outlin_b,
                                          float* __restrict__ out) {
    __shared__ float vi[32 * 68];
    __shared__ float wt[64 * 68];
    const int tid = threadIdx.x;
    const int i0 = blockIdx.x * 32;

#pragma unroll
    for (int u = 0; u < 2; u++) {
        int f4 = tid + 256 * u;
        int r = f4 >> 4, kq = (f4 & 15) * 4;
        float4 xa = *(const float4*)&g_xres[(size_t)(i0 + r) * 64 + kq];
        float4 xb = *(const float4*)&g_attO[(size_t)(i0 + r) * 64 + kq];
        xa.x += xb.x; xa.y += xb.y; xa.z += xb.z; xa.w += xb.w;
        *(float4*)&vi[r * 68 + kq] = xa;
    }
#pragma unroll
    for (int u = 0; u < 16; u++) {
        int idx = tid + 256 * u;
        int k2 = idx >> 6, k = idx & 63;
        wt[k * 68 + k2] = outlin_w[k2 * 64 + k];
    }
    __syncthreads();

    const int r = tid >> 3, g = tid & 7;
    float acc[8];
#pragma unroll
    for (int u = 0; u < 8; u++) acc[u] = 0.f;
#pragma unroll 8
    for (int k = 0; k < 64; k++) {
        float xv = vi[r * 68 + k];
        float4 w0 = *(float4*)&wt[k * 68 + g * 4];
        float4 w1 = *(float4*)&wt[k * 68 + 32 + g * 4];
        acc[0] += xv * w0.x; acc[1] += xv * w0.y;
        acc[2] += xv * w0.z; acc[3] += xv * w0.w;
        acc[4] += xv * w1.x; acc[5] += xv * w1.y;
        acc[6] += xv * w1.z; acc[7] += xv * w1.w;
    }
    float* dst = out + (size_t)(i0 + r) * 64;
    float4 oa = make_float4(elu1(acc[0] + outlin_b[g * 4 + 0]),
                            elu1(acc[1] + outlin_b[g * 4 + 1]),
                            elu1(acc[2] + outlin_b[g * 4 + 2]),
                            elu1(acc[3] + outlin_b[g * 4 + 3]));
    float4 ob = make_float4(elu1(acc[4] + outlin_b[32 + g * 4 + 0]),
                            elu1(acc[5] + outlin_b[32 + g * 4 + 1]),
                            elu1(acc[6] + outlin_b[32 + g * 4 + 2]),
                            elu1(acc[7] + outlin_b[32 + g * 4 + 3]));
    *(float4*)(dst + g * 4) = oa;
    *(float4*)(dst + 32 + g * 4) = ob;
}

// ---------------- launch ----------------
extern "C" void kernel_launch(void* const* d_in, const int* in_sizes, int n_in,
                              void* d_out, int out_size) {
    const float* x        = (const float*)d_in[0];
    const int*   adj      = (const int*)d_in[1];
    const float* w_heads  = (const float*)d_in[2];
    const float* a_heads  = (const float*)d_in[3];
    const float* w_out    = (const float*)d_in[4];
    const float* a_out    = (const float*)d_in[5];
    const float* lin_w    = (const float*)d_in[6];
    const float* lin_b    = (const float*)d_in[7];
    const float* outlin_w = (const float*)d_in[8];
    const float* outlin_b = (const float*)d_in[9];
    float* out = (float*)d_out;

    kA<<<128, 256>>>(x, w_heads, lin_w, lin_b);
    kB<<<2048, 256>>>(a_heads);
    kC<<<dim3(128, 4), 256>>>(adj, 0);   // 4 heads -> g_hcat
    kE<<<256, 256>>>(w_out, a_out);      // out-layer Wh + s,t
    kC<<<dim3(128, 1), 256>>>(adj, 1);   // out layer -> g_attO
    kG<<<128, 256>>>(outlin_w, outlin_b, out);
}

// round 4
// speedup vs baseline: 1.2313x; 1.2313x over previous
#include <cuda_runtime.h>

#define ALPHA 0.2f
#define PS_STRIDE 68
#define WH_STRIDE 68

// ---------------- persistent scratch ----------------
__device__ float g_WhH[4 * 4096 * 64];
__device__ float g_WhO[4096 * 64];
__device__ float g_xres[4096 * 64];
__device__ float g_hcat[4096 * 256];
__device__ float g_part[4 * 4096 * 64];   // mode-1 partial numerators (4 j-slices)
__device__ float g_denp[4 * 4096];        // mode-1 partial denominators
__device__ float g_s[5 * 4096];
__device__ float g_t[5 * 4096];

// ---------------- helpers ----------------
__device__ __forceinline__ float elu1(float v) {
    return v > 0.f ? v : (__expf(v) - 1.f);
}
__device__ __forceinline__ float scorep(float sv, float tv, int m) {
    float e = sv + tv;
    e = e > 0.f ? e : ALPHA * e;
    return m > 0 ? __expf(e) : 0.f;
}
__device__ __forceinline__ unsigned long long pk2(float a) {
    unsigned long long r;
    unsigned int b = __float_as_uint(a);
    asm("mov.b64 %0, {%1, %1};" : "=l"(r) : "r"(b));
    return r;
}
__device__ __forceinline__ void ffma2(unsigned long long& d, unsigned long long a,
                                      unsigned long long b) {
    asm("fma.rn.f32x2 %0, %1, %2, %0;" : "+l"(d) : "l"(a), "l"(b));
}
__device__ __forceinline__ float2 upk(unsigned long long v) {
    unsigned int lo, hi;
    asm("mov.b64 {%0, %1}, %2;" : "=r"(lo), "=r"(hi) : "l"(v));
    return make_float2(__uint_as_float(lo), __uint_as_float(hi));
}
__device__ __forceinline__ void cp16(const void* smem_dst, const void* gsrc) {
    unsigned d = (unsigned)__cvta_generic_to_shared(smem_dst);
    asm volatile("cp.async.cg.shared.global [%0], [%1], 16;" :: "r"(d), "l"(gsrc));
}

// ---------------- Kernel A: Wh for 4 heads + x_residual + per-head s,t ----------------
__global__ __launch_bounds__(256) void kA(const float* __restrict__ x,
                                          const float* __restrict__ w_heads,
                                          const float* __restrict__ lin_w,
                                          const float* __restrict__ lin_b,
                                          const float* __restrict__ a_heads) {
    __shared__ float xs[32 * 132];
    __shared__ float ws[64 * 68];
    __shared__ float as_[4 * 128];
    const int tid = threadIdx.x;
    const int i0 = blockIdx.x * 32;

#pragma unroll
    for (int u = 0; u < 16; u++) {
        int idx = tid + 256 * u;
        int r = idx >> 7, f = idx & 127;
        xs[r * 132 + f] = x[(i0 + r) * 128 + f];
    }
#pragma unroll
    for (int u = 0; u < 2; u++) {
        int idx = tid + 256 * u;
        as_[idx] = a_heads[idx];
    }

    const int r = tid >> 3, g = tid & 7;

    for (int cc = 0; cc < 5; cc++) {
        float acc[8];
#pragma unroll
        for (int u = 0; u < 8; u++) acc[u] = 0.f;

        for (int fh = 0; fh < 2; fh++) {
            __syncthreads();
            if (cc < 4) {
#pragma unroll
                for (int u = 0; u < 4; u++) {
                    int f4 = tid + 256 * u;
                    int jj = f4 >> 4, kq = (f4 & 15) * 4;
                    *(float4*)&ws[jj * 68 + kq] =
                        *(const float4*)&w_heads[(cc * 128 + fh * 64 + jj) * 64 + kq];
                }
            } else {
#pragma unroll
                for (int u = 0; u < 16; u++) {
                    int idx = tid + 256 * u;
                    int k = idx >> 6, fo = idx & 63;
                    ws[fo * 68 + k] = lin_w[k * 128 + fh * 64 + fo];
                }
            }
            __syncthreads();
#pragma unroll 8
            for (int fo = 0; fo < 64; fo++) {
                float xv = xs[r * 132 + fh * 64 + fo];
                float4 w0 = *(float4*)&ws[fo * 68 + g * 4];
                float4 w1 = *(float4*)&ws[fo * 68 + 32 + g * 4];
                acc[0] += xv * w0.x; acc[1] += xv * w0.y;
                acc[2] += xv * w0.z; acc[3] += xv * w0.w;
                acc[4] += xv * w1.x; acc[5] += xv * w1.y;
                acc[6] += xv * w1.z; acc[7] += xv * w1.w;
            }
        }

        if (cc < 4) {
            float* dst = g_WhH + ((size_t)(cc * 4096) + i0 + r) * 64;
            *(float4*)(dst + g * 4) = make_float4(acc[0], acc[1], acc[2], acc[3]);
            *(float4*)(dst + 32 + g * 4) = make_float4(acc[4], acc[5], acc[6], acc[7]);
            // fused s,t: dot with a_heads[cc]
            const float* av = as_ + cc * 128;
            float sp = 0.f, tp = 0.f;
#pragma unroll
            for (int u = 0; u < 4; u++) {
                int c0 = g * 4 + u, c1 = 32 + g * 4 + u;
                sp += acc[u] * av[c0] + acc[4 + u] * av[c1];
                tp += acc[u] * av[64 + c0] + acc[4 + u] * av[64 + c1];
            }
            sp += __shfl_xor_sync(0xffffffffu, sp, 1);
            sp += __shfl_xor_sync(0xffffffffu, sp, 2);
            sp += __shfl_xor_sync(0xffffffffu, sp, 4);
            tp += __shfl_xor_sync(0xffffffffu, tp, 1);
            tp += __shfl_xor_sync(0xffffffffu, tp, 2);
            tp += __shfl_xor_sync(0xffffffffu, tp, 4);
            if (g == 0) {
                g_s[cc * 4096 + i0 + r] = sp;
                g_t[cc * 4096 + i0 + r] = tp;
            }
        } else {
            float* dst = g_xres + ((size_t)(i0 + r)) * 64;
            float4 oa = make_float4(acc[0] + lin_b[g * 4 + 0], acc[1] + lin_b[g * 4 + 1],
                                    acc[2] + lin_b[g * 4 + 2], acc[3] + lin_b[g * 4 + 3]);
            float4 ob = make_float4(acc[4] + lin_b[32 + g * 4 + 0], acc[5] + lin_b[32 + g * 4 + 1],
                                    acc[6] + lin_b[32 + g * 4 + 2], acc[7] + lin_b[32 + g * 4 + 3]);
            *(float4*)(dst + g * 4) = oa;
            *(float4*)(dst + 32 + g * 4) = ob;
        }
    }
}

// ---------------- Kernel C: fused masked-softmax aggregation, 128-row tiles, pipelined ----------------
// mode 0: blockIdx.y = head, full j-range, write elu -> g_hcat
// mode 1: blockIdx.y = j-slice (1024 wide), write raw partials -> g_part/g_denp
extern __shared__ float smemC[];

__global__ __launch_bounds__(256, 1) void kC(const int* __restrict__ adj, int mode) {
    float* whs = smemC;                          // 2 * 64 * 68
    float* Ps  = smemC + 2 * 64 * WH_STRIDE;     // 2 * 128 * 68
    float* dh  = Ps + 2 * 128 * PS_STRIDE;       // 256

    const int tid = threadIdx.x;
    const int i0 = blockIdx.x * 128;

    const float *Wh, *sh, *th;
    int jlo, T, hb = 0, sl = 0;
    if (mode == 0) {
        hb = blockIdx.y;
        Wh = g_WhH + (size_t)hb * 4096 * 64;
        sh = g_s + hb * 4096;
        th = g_t + hb * 4096;
        jlo = 0; T = 64;
    } else {
        sl = blockIdx.y;
        Wh = g_WhO;
        sh = g_s + 4 * 4096;
        th = g_t + 4 * 4096;
        jlo = sl * 1024; T = 16;
    }

    // phase-1 mapping: 2 threads per row
    const int r2 = tid >> 1, half = tid & 1;
    const float sv = sh[i0 + r2];
    const int* arow = adj + (size_t)(i0 + r2) * 4096 + half * 32;
    const float* trow = th + half * 32;

    // phase-2 mapping: rows lane+32rr, cols wq*4..+3 and 32+wq*4..+3
    const int lane = tid & 31, wq = tid >> 5;

    unsigned long long acc[16];
#pragma unroll
    for (int u = 0; u < 16; u++) acc[u] = 0ull;
    float dpart = 0.f;

    int4 areg[8];
    float4 treg[8];

    // ---- stage tile 0 (whs via cp.async), prefetch adj/t tile 0 ----
    {
        const int j0 = jlo;
#pragma unroll
        for (int u = 0; u < 4; u++) {
            int c = tid + 256 * u;
            int jj = c >> 4, q = c & 15;
            cp16(whs + jj * WH_STRIDE + q * 4, Wh + (size_t)(j0 + jj) * 64 + q * 4);
        }
        asm volatile("cp.async.commit_group;");
#pragma unroll
        for (int u = 0; u < 8; u++) {
            areg[u] = *(const int4*)(arow + j0 + u * 4);
            treg[u] = *(const float4*)(trow + j0 + u * 4);
        }
        asm volatile("cp.async.wait_group 0;");
        // phase 1 for tile 0
        float dadd = 0.f;
        float* Pd = Ps + r2 * PS_STRIDE + half * 32;
#pragma unroll
        for (int u = 0; u < 8; u++) {
            int4 a = areg[u]; float4 tv = treg[u];
            float4 p;
            p.x = scorep(sv, tv.x, a.x);
            p.y = scorep(sv, tv.y, a.y);
            p.z = scorep(sv, tv.z, a.z);
            p.w = scorep(sv, tv.w, a.w);
            *(float4*)(Pd + u * 4) = p;
            dadd += (p.x + p.y) + (p.z + p.w);
        }
        dpart += dadd;
    }

    for (int t = 0; t < T; t++) {
        const int buf = t & 1, nbuf = 1 - buf;
        if (t + 1 < T) {
            const int j0n = jlo + (t + 1) * 64;
#pragma unroll
            for (int u = 0; u < 4; u++) {
                int c = tid + 256 * u;
                int jj = c >> 4, q = c & 15;
                cp16(whs + nbuf * (64 * WH_STRIDE) + jj * WH_STRIDE + q * 4,
                     Wh + (size_t)(j0n + jj) * 64 + q * 4);
            }
            asm volatile("cp.async.commit_group;");
#pragma unroll
            for (int u = 0; u < 8; u++) {
                areg[u] = *(const int4*)(arow + j0n + u * 4);
                treg[u] = *(const float4*)(trow + j0n + u * 4);
            }
        }
        __syncthreads();

        // ---- phase 2: acc += P[buf] * whs[buf] ----
        const float* Wb = whs + buf * (64 * WH_STRIDE) + wq * 4;
        const float* Pr = Ps + buf * (128 * PS_STRIDE) + lane * PS_STRIDE;
#pragma unroll 4
        for (int q = 0; q < 16; q++) {
            float p0[4], p1[4], p2[4], p3[4];
            *(float4*)p0 = *(const float4*)(Pr + q * 4);
            *(float4*)p1 = *(const float4*)(Pr + 32 * PS_STRIDE + q * 4);
            *(float4*)p2 = *(const float4*)(Pr + 64 * PS_STRIDE + q * 4);
            *(float4*)p3 = *(const float4*)(Pr + 96 * PS_STRIDE + q * 4);
#pragma unroll
            for (int u = 0; u < 4; u++) {
                const float* wr = Wb + (q * 4 + u) * WH_STRIDE;
                ulonglong2 wA = *(const ulonglong2*)wr;
                ulonglong2 wB = *(const ulonglong2*)(wr + 32);
                unsigned long long v0 = pk2(p0[u]);
                ffma2(acc[0], v0, wA.x); ffma2(acc[1], v0, wA.y);
                ffma2(acc[2], v0, wB.x); ffma2(acc[3], v0, wB.y);
                unsigned long long v1 = pk2(p1[u]);
                ffma2(acc[4], v1, wA.x); ffma2(acc[5], v1, wA.y);
                ffma2(acc[6], v1, wB.x); ffma2(acc[7], v1, wB.y);
                unsigned long long v2 = pk2(p2[u]);
                ffma2(acc[8], v2, wA.x); ffma2(acc[9], v2, wA.y);
                ffma2(acc[10], v2, wB.x); ffma2(acc[11], v2, wB.y);
                unsigned long long v3 = pk2(p3[u]);
                ffma2(acc[12], v3, wA.x); ffma2(acc[13], v3, wA.y);
                ffma2(acc[14], v3, wB.x); ffma2(acc[15], v3, wB.y);
            }
        }

        if (t + 1 < T) {
            asm volatile("cp.async.wait_group 0;");
            // ---- phase 1 for tile t+1 ----
            float dadd = 0.f;
            float* Pd = Ps + nbuf * (128 * PS_STRIDE) + r2 * PS_STRIDE + half * 32;
#pragma unroll
            for (int u = 0; u < 8; u++) {
                int4 a = areg[u]; float4 tv = treg[u];
                float4 p;
                p.x = scorep(sv, tv.x, a.x);
                p.y = scorep(sv, tv.y, a.y);
                p.z = scorep(sv, tv.z, a.z);
                p.w = scorep(sv, tv.w, a.w);
                *(float4*)(Pd + u * 4) = p;
                dadd += (p.x + p.y) + (p.z + p.w);
            }
            dpart += dadd;
        }
    }

    // denominators
    dh[tid] = dpart;   // dh[2*row + half]
    __syncthreads();

#pragma unroll
    for (int rr = 0; rr < 4; rr++) {
        int row = lane + rr * 32;
        float dden = dh[2 * row] + dh[2 * row + 1];
        float2 c0 = upk(acc[rr * 4 + 0]);
        float2 c1 = upk(acc[rr * 4 + 1]);
        float2 c2 = upk(acc[rr * 4 + 2]);
        float2 c3 = upk(acc[rr * 4 + 3]);
        if (mode == 0) {
            float dinv = 1.f / dden;
            float* dst = g_hcat + (size_t)(i0 + row) * 256 + hb * 64;
            *(float4*)(dst + wq * 4) =
                make_float4(elu1(c0.x * dinv), elu1(c0.y * dinv),
                            elu1(c1.x * dinv), elu1(c1.y * dinv));
            *(float4*)(dst + 32 + wq * 4) =
                make_float4(elu1(c2.x * dinv), elu1(c2.y * dinv),
                            elu1(c3.x * dinv), elu1(c3.y * dinv));
        } else {
            float* dst = g_part + ((size_t)sl * 4096 + i0 + row) * 64;
            *(float4*)(dst + wq * 4) = make_float4(c0.x, c0.y, c1.x, c1.y);
            *(float4*)(dst + 32 + wq * 4) = make_float4(c2.x, c2.y, c3.x, c3.y);
            if (wq == 0) g_denp[sl * 4096 + i0 + row] = dden;
        }
    }
}

// ---------------- Kernel E: out-layer Wh = hcat @ w_out, plus s,t ----------------
__global__ __launch_bounds__(256) void kE(const float* __restrict__ w_out,
                                          const float* __restrict__ a_out) {
    __shared__ float hc[16 * 260];
    __shared__ float ws[64 * 68];
    const int tid = threadIdx.x;
    const int i0 = blockIdx.x * 16;

#pragma unroll
    for (int u = 0; u < 4; u++) {
        int f4 = tid + 256 * u;
        int r = f4 >> 6, cq = (f4 & 63) * 4;
        *(float4*)&hc[r * 260 + cq] = *(const float4*)&g_hcat[(size_t)(i0 + r) * 256 + cq];
    }

    const int r2 = tid >> 4, g2 = tid & 15;
    float acc[4] = {0.f, 0.f, 0.f, 0.f};

    for (int fc = 0; fc < 4; fc++) {
        __syncthreads();
#pragma unroll
        for (int u = 0; u < 4; u++) {
            int f4 = tid + 256 * u;
            int jj = f4 >> 4, kq = (f4 & 15) * 4;
            *(float4*)&ws[jj * 68 + kq] = *(const float4*)&w_out[(fc * 64 + jj) * 64 + kq];
        }
        __syncthreads();
#pragma unroll 8
        for (int fo = 0; fo < 64; fo++) {
            float xv = hc[r2 * 260 + fc * 64 + fo];
            float4 wv = *(float4*)&ws[fo * 68 + g2 * 4];
            acc[0] += xv * wv.x; acc[1] += xv * wv.y;
            acc[2] += xv * wv.z; acc[3] += xv * wv.w;
        }
    }

    float* dst = g_WhO + (size_t)(i0 + r2) * 64 + g2 * 4;
    *(float4*)dst = make_float4(acc[0], acc[1], acc[2], acc[3]);
    __syncthreads();

    if (tid < 16) {
        const float* wr = g_WhO + (size_t)(i0 + tid) * 64;
        float sAcc = 0.f, tAcc = 0.f;
        for (int k = 0; k < 64; k++) {
            float v = wr[k];
            sAcc += v * a_out[k];
            tAcc += v * a_out[64 + k];
        }
        g_s[4 * 4096 + i0 + tid] = sAcc;
        g_t[4 * 4096 + i0 + tid] = tAcc;
    }
}

// ---------------- Kernel G: combine mode-1 partials + final linear + elu ----------------
__global__ __launch_bounds__(256) void kG(const float* __restrict__ outlin_w,
                                          const float* __restrict__ outlin_b,
                                          float* __restrict__ out) {
    __shared__ float vi[32 * 68];
    __shared__ float wt[64 * 68];
    const int tid = threadIdx.x;
    const int i0 = blockIdx.x * 32;

#pragma unroll
    for (int u = 0; u < 2; u++) {
        int f4 = tid + 256 * u;
        int r = f4 >> 4, kq = (f4 & 15) * 4;
        int row = i0 + r;
        float4 xa = *(const float4*)&g_xres[(size_t)row * 64 + kq];
        float4 n = *(const float4*)&g_part[((size_t)0 * 4096 + row) * 64 + kq];
        float4 n1 = *(const float4*)&g_part[((size_t)1 * 4096 + row) * 64 + kq];
        float4 n2 = *(const float4*)&g_part[((size_t)2 * 4096 + row) * 64 + kq];
        float4 n3 = *(const float4*)&g_part[((size_t)3 * 4096 + row) * 64 + kq];
        n.x += n1.x + n2.x + n3.x;
        n.y += n1.y + n2.y + n3.y;
        n.z += n1.z + n2.z + n3.z;
        n.w += n1.w + n2.w + n3.w;
        float ds = g_denp[row] + g_denp[4096 + row] + g_denp[2 * 4096 + row] +
                   g_denp[3 * 4096 + row];
        float di = 1.f / ds;
        xa.x += elu1(n.x * di);
        xa.y += elu1(n.y * di);
        xa.z += elu1(n.z * di);
        xa.w += elu1(n.w * di);
        *(float4*)&vi[r * 68 + kq] = xa;
    }
#pragma unroll
    for (int u = 0; u < 16; u++) {
        int idx = tid + 256 * u;
        int k2 = idx >> 6, k = idx & 63;
        wt[k * 68 + k2] = outlin_w[k2 * 64 + k];
    }
    __syncthreads();

    const int r = tid >> 3, g = tid & 7;
    float acc[8];
#pragma unroll
    for (int u = 0; u < 8; u++) acc[u] = 0.f;
#pragma unroll 8
    for (int k = 0; k < 64; k++) {
        float xv = vi[r * 68 + k];
        float4 w0 = *(float4*)&wt[k * 68 + g * 4];
        float4 w1 = *(float4*)&wt[k * 68 + 32 + g * 4];
        acc[0] += xv * w0.x; acc[1] += xv * w0.y;
        acc[2] += xv * w0.z; acc[3] += xv * w0.w;
        acc[4] += xv * w1.x; acc[5] += xv * w1.y;
        acc[6] += xv * w1.z; acc[7] += xv * w1.w;
    }
    float* dst = out + (size_t)(i0 + r) * 64;
    float4 oa = make_float4(elu1(acc[0] + outlin_b[g * 4 + 0]),
                            elu1(acc[1] + outlin_b[g * 4 + 1]),
                            elu1(acc[2] + outlin_b[g * 4 + 2]),
                            elu1(acc[3] + outlin_b[g * 4 + 3]));
    float4 ob = make_float4(elu1(acc[4] + outlin_b[32 + g * 4 + 0]),
                            elu1(acc[5] + outlin_b[32 + g * 4 + 1]),
                            elu1(acc[6] + outlin_b[32 + g * 4 + 2]),
                            elu1(acc[7] + outlin_b[32 + g * 4 + 3]));
    *(float4*)(dst + g * 4) = oa;
    *(float4*)(dst + 32 + g * 4) = ob;
}

// ---------------- launch ----------------
extern "C" void kernel_launch(void* const* d_in, const int* in_sizes, int n_in,
                              void* d_out, int out_size) {
    const float* x        = (const float*)d_in[0];
    const int*   adj      = (const int*)d_in[1];
    const float* w_heads  = (const float*)d_in[2];
    const float* a_heads  = (const float*)d_in[3];
    const float* w_out    = (const float*)d_in[4];
    const float* a_out    = (const float*)d_in[5];
    const float* lin_w    = (const float*)d_in[6];
    const float* lin_b    = (const float*)d_in[7];
    const float* outlin_w = (const float*)d_in[8];
    const float* outlin_b = (const float*)d_in[9];
    float* out = (float*)d_out;

    const int SMEM_C = (2 * 64 * WH_STRIDE + 2 * 128 * PS_STRIDE + 256) * 4;
    cudaFuncSetAttribute(kC, cudaFuncAttributeMaxDynamicSharedMemorySize, SMEM_C);

    kA<<<128, 256>>>(x, w_heads, lin_w, lin_b, a_heads);
    kC<<<dim3(32, 4), 256, SMEM_C>>>(adj, 0);   // 4 heads, full j-range -> g_hcat
    kE<<<256, 256>>>(w_out, a_out);             // out-layer Wh + s,t
    kC<<<dim3(32, 4), 256, SMEM_C>>>(adj, 1);   // out layer, 4 j-slices -> partials
    kG<<<128, 256>>>(outlin_w, outlin_b, out);  // combine + final linear + elu
}